// round 9
// baseline (speedup 1.0000x reference)
#include <cuda_runtime.h>
#include <cuda_fp16.h>
#include <cstdint>
#include <math.h>

#define B_ 8
#define S_ 2048
#define D_ 256
#define H_ 4
#define DH_ 64

#define QKV_ELEMS ((size_t)B_ * H_ * S_ * DH_)
#define CTX_ELEMS ((size_t)B_ * S_ * D_)

// Scratch (allocation-free rule: __device__ globals)
__device__ __half g_q16h[QKV_ELEMS];   // [b,h,s,dh], pre-scaled by log2e/8
__device__ __half g_k16h[QKV_ELEMS];   // [b,h,s,dh]
__device__ __half g_v16h[QKV_ELEMS];   // [b,h,s,dh]  (ldsm.trans in attention)
__device__ __half g_ctxh[CTX_ELEMS];   // [b*s, 256]
__device__ __half g_ctxl[CTX_ELEMS];
__device__ __half g_w16h[4 * 256 * 256];  // [mat][n][k] transposed, mats: q,k,v,o
__device__ __half g_w16l[4 * 256 * 256];

// ---------------------------------------------------------------------------
// helpers
// ---------------------------------------------------------------------------
__device__ __forceinline__ uint32_t smem_u32(const void* p) {
    uint32_t a;
    asm("{ .reg .u64 t; cvta.to.shared.u64 t, %1; cvt.u32.u64 %0, t; }"
        : "=r"(a) : "l"(p));
    return a;
}
__device__ __forceinline__ uint32_t swz128(uint32_t x) {
    return x ^ ((x >> 3) & 0x70);
}
__device__ __forceinline__ void ldsm_x4(uint32_t* r, uint32_t addr) {
    asm volatile("ldmatrix.sync.aligned.m8n8.x4.shared.b16 {%0,%1,%2,%3}, [%4];"
                 : "=r"(r[0]), "=r"(r[1]), "=r"(r[2]), "=r"(r[3]) : "r"(addr));
}
__device__ __forceinline__ void ldsm_x4t(uint32_t* r, uint32_t addr) {
    asm volatile("ldmatrix.sync.aligned.m8n8.x4.trans.shared.b16 {%0,%1,%2,%3}, [%4];"
                 : "=r"(r[0]), "=r"(r[1]), "=r"(r[2]), "=r"(r[3]) : "r"(addr));
}
__device__ __forceinline__ void mma16816(float* c, const uint32_t* a, const uint32_t* b) {
    asm volatile("mma.sync.aligned.m16n8k16.row.col.f32.f16.f16.f32 "
                 "{%0,%1,%2,%3}, {%4,%5,%6,%7}, {%8,%9}, {%0,%1,%2,%3};"
                 : "+f"(c[0]), "+f"(c[1]), "+f"(c[2]), "+f"(c[3])
                 : "r"(a[0]), "r"(a[1]), "r"(a[2]), "r"(a[3]),
                   "r"(b[0]), "r"(b[1]));
}
__device__ __forceinline__ uint32_t pack_h2(float lo, float hi) {
    __half2 h = __floats2half2_rn(lo, hi);
    return *reinterpret_cast<uint32_t*>(&h);
}
__device__ __forceinline__ uint32_t ex2_h2(uint32_t a) {
    uint32_t d;
    asm("ex2.approx.f16x2 %0, %1;" : "=r"(d) : "r"(a));
    return d;
}
__device__ __forceinline__ void cpa16(uint32_t dst, const void* src) {
    asm volatile("cp.async.cg.shared.global [%0], [%1], 16;"
                 :: "r"(dst), "l"(src) : "memory");
}
#define CPA_COMMIT asm volatile("cp.async.commit_group;" ::: "memory")
#define CPA_WAIT2 asm volatile("cp.async.wait_group 2;" ::: "memory")
#define CPA_WAIT1 asm volatile("cp.async.wait_group 1;" ::: "memory")
#define CPA_WAIT0 asm volatile("cp.async.wait_group 0;" ::: "memory")

// ---------------------------------------------------------------------------
// One-time weight conversion: fp32 [k][n] -> fp16 hi/lo transposed [n][k]
// ---------------------------------------------------------------------------
__global__ __launch_bounds__(256) void conv_w(
    const float* __restrict__ wq, const float* __restrict__ wk,
    const float* __restrict__ wv, const float* __restrict__ wo)
{
    const int mat = blockIdx.y;
    const float* w = (mat == 0) ? wq : (mat == 1) ? wk : (mat == 2) ? wv : wo;
    int idx = blockIdx.x * 256 + threadIdx.x;
    int n = idx >> 8, k = idx & 255;
    float v = w[k * 256 + n];
    __half hi = __float2half_rn(v);
    g_w16h[mat * 65536 + idx] = hi;
    g_w16l[mat * 65536 + idx] = __float2half_rn(v - __half2float(hi));
}

// ---------------------------------------------------------------------------
// shared GEMM smem layout (192KB)
// ---------------------------------------------------------------------------
#define GX_H 0
#define GX_L 65536
#define GW_H 131072      // qkv: 2 chunk buffers x 32KB; out: hi slab
#define GW_L 163840
#define GEMM_SMEM 196608

#define BROW_OFF ((lane & 7) + ((lane & 16) >> 1))
#define BCOL_OFF ((lane & 8) << 1)

__device__ __forceinline__ void load_w_slab(uint32_t sb, const __half* wh,
                                            const __half* wl, int tid) {
#pragma unroll
    for (int i = tid; i < 2048; i += 256) {
        int r = i >> 5, c = i & 31;
        uint32_t so = (uint32_t)(c >> 3) * 8192 +
                      swz128((uint32_t)(r * 128 + ((c & 7) << 4)));
        cpa16(sb + GW_H + so, wh + r * 256 + c * 8);
        cpa16(sb + GW_L + so, wl + r * 256 + c * 8);
    }
}

// qkv W chunk: 64 n-rows x 128 k (k-half kh), hi+lo -> 32KB chunk buffer
__device__ __forceinline__ void load_w_chunk(uint32_t dst, const __half* wh,
                                             const __half* wl, int kh, int tid) {
#pragma unroll
    for (int i = tid; i < 1024; i += 256) {
        int r = i >> 4, cp = i & 15;
        uint32_t so = (uint32_t)(cp >> 3) * 8192 +
                      swz128((uint32_t)(r * 128 + ((cp & 7) << 4)));
        int gof = r * 256 + (kh * 16 + cp) * 8;
        cpa16(dst + so, wh + gof);
        cpa16(dst + 16384 + so, wl + gof);
    }
}

// ---------------------------------------------------------------------------
// Fused QKV projection, fp16 HMMA, 3-term split, pipelined W chunks.
// 8 chunks = (4 n-slabs) x (2 k-halves), ping-pong buffers in GW region.
// ---------------------------------------------------------------------------
__global__ __launch_bounds__(256) void qkv_hmma(const float* __restrict__ x)
{
    extern __shared__ __align__(1024) char smem[];
    const int tid = threadIdx.x;
    const int wid = tid >> 5, lane = tid & 31;
    const int m0 = blockIdx.x * 128;
    const int z = blockIdx.z;
    const uint32_t sb = smem_u32(smem);

    const __half* wbh = g_w16h + z * 65536;
    const __half* wbl = g_w16l + z * 65536;

    // start chunk 0 DMA first
    load_w_chunk(sb + GW_H, wbh, wbl, 0, tid);
    CPA_COMMIT;

    // X tile: fp32 -> fp16 hi/lo panels
    for (int i = tid; i < 8192; i += 256) {
        int r = i >> 6;
        int kc = (i & 63) << 2;
        float4 v = *reinterpret_cast<const float4*>(x + (size_t)(m0 + r) * 256 + kc);
        float hx = __half2float(__float2half_rn(v.x));
        float hy = __half2float(__float2half_rn(v.y));
        float hz = __half2float(__float2half_rn(v.z));
        float hw = __half2float(__float2half_rn(v.w));
        uint32_t so = (uint32_t)(kc >> 6) * 16384 +
                      swz128((uint32_t)(r * 128 + (kc & 63) * 2));
        *(uint32_t*)(smem + GX_H + so)     = pack_h2(hx, hy);
        *(uint32_t*)(smem + GX_H + so + 4) = pack_h2(hz, hw);
        *(uint32_t*)(smem + GX_L + so)     = pack_h2(v.x - hx, v.y - hy);
        *(uint32_t*)(smem + GX_L + so + 4) = pack_h2(v.z - hz, v.w - hw);
    }

    const int b = m0 >> 11;
    const int row0 = m0 + wid * 16 + (lane >> 2);
    const int s0 = row0 & 2047;
    const float QSCALE = 0.125f * 1.44269504f;   // 1/sqrt(64) * log2(e)

    float acc[8][4];

    for (int c = 0; c < 8; c++) {
        const int nb = c >> 1, kh = c & 1;
        if (c + 1 < 8) {
            load_w_chunk(sb + GW_H + ((c + 1) & 1) * 32768,
                         wbh + (c + 1 >> 1) * 64 * 256,
                         wbl + (c + 1 >> 1) * 64 * 256, (c + 1) & 1, tid);
            CPA_COMMIT;
            CPA_WAIT1;
        } else {
            CPA_WAIT0;
        }
        __syncthreads();

        if (kh == 0) {
#pragma unroll
            for (int j = 0; j < 8; j++)
#pragma unroll
                for (int e = 0; e < 4; e++) acc[j][e] = 0.f;
        }

        const uint32_t wb = sb + GW_H + (c & 1) * 32768;
#pragma unroll
        for (int kk = 0; kk < 8; kk++) {
            const int kk2 = kh * 8 + kk;
            uint32_t aoff = (uint32_t)(kk2 >> 2) * 16384 +
                swz128((uint32_t)((wid * 16 + (lane & 15)) * 128 +
                                  (kk2 & 3) * 32 + (lane >> 4) * 16));
            uint32_t ah[4], al[4];
            ldsm_x4(ah, sb + GX_H + aoff);
            ldsm_x4(al, sb + GX_L + aoff);
#pragma unroll
            for (int j = 0; j < 4; j++) {
                uint32_t boff = (uint32_t)(kk >> 2) * 8192 +
                    swz128((uint32_t)((16 * j + BROW_OFF) * 128 +
                                      (kk & 3) * 32 + BCOL_OFF));
                uint32_t bh[4], bl[4];
                ldsm_x4(bh, wb + boff);
                ldsm_x4(bl, wb + 16384 + boff);
                mma16816(acc[2 * j], ah, bh);
                mma16816(acc[2 * j], ah, bl);
                mma16816(acc[2 * j], al, bh);
                mma16816(acc[2 * j + 1], ah, bh + 2);
                mma16816(acc[2 * j + 1], ah, bl + 2);
                mma16816(acc[2 * j + 1], al, bh + 2);
            }
        }

        if (kh == 1) {
            const int h = nb;
            if (z == 0) {
                __half* q = g_q16h + ((size_t)(b * H_ + h) * S_) * DH_;
#pragma unroll
                for (int j = 0; j < 8; j++) {
                    int d = j * 8 + (lane & 3) * 2;
                    *(uint32_t*)&q[(size_t)s0 * DH_ + d] =
                        pack_h2(acc[j][0] * QSCALE, acc[j][1] * QSCALE);
                    *(uint32_t*)&q[(size_t)(s0 + 8) * DH_ + d] =
                        pack_h2(acc[j][2] * QSCALE, acc[j][3] * QSCALE);
                }
            } else {
                __half* dst = ((z == 1) ? g_k16h : g_v16h) +
                              ((size_t)(b * H_ + h) * S_) * DH_;
#pragma unroll
                for (int j = 0; j < 8; j++) {
                    int d = j * 8 + (lane & 3) * 2;
                    *(uint32_t*)&dst[(size_t)s0 * DH_ + d] =
                        pack_h2(acc[j][0], acc[j][1]);
                    *(uint32_t*)&dst[(size_t)(s0 + 8) * DH_ + d] =
                        pack_h2(acc[j][2], acc[j][3]);
                }
            }
        }
        __syncthreads();
    }
}

// ---------------------------------------------------------------------------
// Output projection, fp16 HMMA, 3-term split.
// ---------------------------------------------------------------------------
__global__ __launch_bounds__(256) void out_hmma(
    const float* __restrict__ bo, float* __restrict__ out)
{
    extern __shared__ __align__(1024) char smem[];
    const int tid = threadIdx.x;
    const int wid = tid >> 5, lane = tid & 31;
    const int m0 = blockIdx.x * 128;
    const int n0 = blockIdx.y * 64;
    const uint32_t sb = smem_u32(smem);

    for (int i = tid; i < 4096; i += 256) {
        int r = i >> 5, c = i & 31;
        uint32_t so = (uint32_t)(c >> 3) * 16384 +
                      swz128((uint32_t)(r * 128 + ((c & 7) << 4)));
        cpa16(sb + GX_H + so, g_ctxh + (size_t)(m0 + r) * 256 + c * 8);
        cpa16(sb + GX_L + so, g_ctxl + (size_t)(m0 + r) * 256 + c * 8);
    }
    load_w_slab(sb, g_w16h + 3 * 65536 + n0 * 256,
                    g_w16l + 3 * 65536 + n0 * 256, tid);
    CPA_COMMIT; CPA_WAIT0;
    __syncthreads();

    float acc[8][4] = {};
#pragma unroll
    for (int kk = 0; kk < 16; kk++) {
        uint32_t aoff = (uint32_t)(kk >> 2) * 16384 +
            swz128((uint32_t)((wid * 16 + (lane & 15)) * 128 +
                              (kk & 3) * 32 + (lane >> 4) * 16));
        uint32_t ah[4], al[4];
        ldsm_x4(ah, sb + GX_H + aoff);
        ldsm_x4(al, sb + GX_L + aoff);
#pragma unroll
        for (int j = 0; j < 4; j++) {
            uint32_t boff = (uint32_t)(kk >> 2) * 8192 +
                swz128((uint32_t)((16 * j + BROW_OFF) * 128 +
                                  (kk & 3) * 32 + BCOL_OFF));
            uint32_t bh[4], bl[4];
            ldsm_x4(bh, sb + GW_H + boff);
            ldsm_x4(bl, sb + GW_L + boff);
            mma16816(acc[2 * j], ah, bh);
            mma16816(acc[2 * j], ah, bl);
            mma16816(acc[2 * j], al, bh);
            mma16816(acc[2 * j + 1], ah, bh + 2);
            mma16816(acc[2 * j + 1], ah, bl + 2);
            mma16816(acc[2 * j + 1], al, bh + 2);
        }
    }

    const int row0 = m0 + wid * 16 + (lane >> 2);
#pragma unroll
    for (int j = 0; j < 8; j++) {
        int n = n0 + j * 8 + (lane & 3) * 2;
        float2 bias = *reinterpret_cast<const float2*>(bo + n);
        float2 v0 = {acc[j][0] + bias.x, acc[j][1] + bias.y};
        float2 v1 = {acc[j][2] + bias.x, acc[j][3] + bias.y};
        *reinterpret_cast<float2*>(out + (size_t)row0 * 256 + n) = v0;
        *reinterpret_cast<float2*>(out + (size_t)(row0 + 8) * 256 + n) = v1;
    }
}

// ---------------------------------------------------------------------------
// fp16 HMMA flash attention, 2-D warp tiling (4m x 2n).
// Warp (mi, ni) = 32 q-rows x 64 kv of each 128-tile: K/V smem traffic per
// CTA-tile drops 288KB -> 160KB (smem-crossbar was the binding resource).
// Fixed softmax max m=0 (log2-domain scores, ex2.approx.f16x2) makes the two
// kv-groups' (O, l) partials exactly additive -> one smem reduction at end.
// 3-stage cp.async KV ring (112KB smem).
// ---------------------------------------------------------------------------
#define MQ 128
#define NKV 128

#define QH_OFF 0            // 128 x 128B  (Q hi, fp16, scaled)
#define BUF_BASE 16384      // 3 buffers x 32KB
#define KBH 0               // K tile 16KB (128 kv x 128B)
#define VBH 16384           // V tile 16KB (128 kv x 128B)
#define BUF_SZ 32768
#define NSTAGE 3
#define ATTN_SMEM (16384 + NSTAGE * BUF_SZ)
#define NT (S_ / NKV)

__global__ __launch_bounds__(256) void attn_kernel()
{
    extern __shared__ __align__(1024) char smem[];
    const int tid = threadIdx.x;
    const int wid = tid >> 5, lane = tid & 31;
    const int mi = wid & 3, ni = wid >> 2;
    const int mrow = mi * 32;
    const int qt = blockIdx.x, h = blockIdx.y, b = blockIdx.z;
    const uint32_t sb = smem_u32(smem);

    const size_t hb = (size_t)(b * H_ + h);
    const char* qh  = (const char*)(g_q16h + (hb * S_ + (size_t)qt * MQ) * DH_);
    const char* kh0 = (const char*)(g_k16h + hb * S_ * DH_);
    const char* vh0 = (const char*)(g_v16h + hb * S_ * DH_);

    const int kr = tid >> 3, kc = (tid & 7) << 4;

    auto prefetch = [&](int t, uint32_t bb) {
        const char* kh = kh0 + (size_t)t * 128 * 128;
        const char* vh = vh0 + (size_t)t * 128 * 128;
#pragma unroll
        for (int s = 0; s < 4; s++) {
            int r = kr + s * 32;
            uint32_t so = swz128((uint32_t)(r * 128 + kc));
            cpa16(bb + KBH + so, kh + r * 128 + kc);
            cpa16(bb + VBH + so, vh + r * 128 + kc);
        }
    };

    prefetch(0, sb + BUF_BASE);
    CPA_COMMIT;

    for (int i = tid; i < 1024; i += 256) {
        int r = i >> 3, c = (i & 7) << 4;
        uint32_t so = swz128((uint32_t)(r * 128 + c));
        *(float4*)(smem + QH_OFF + so) = *(const float4*)(qh + r * 128 + c);
    }

    prefetch(1, sb + BUF_BASE + BUF_SZ);
    CPA_COMMIT;
    __syncthreads();   // Q visible

    // Q A-fragments: 2 strips (m16) x 4 k-steps
    uint32_t aqh[2][4][4];
#pragma unroll
    for (int st = 0; st < 2; st++)
#pragma unroll
        for (int kk = 0; kk < 4; kk++) {
            uint32_t off = swz128((uint32_t)((mrow + st * 16 + (lane & 15)) * 128 +
                                             kk * 32 + (lane >> 4) * 16));
            ldsm_x4(aqh[st][kk], sb + QH_OFF + off);
        }

    const int brow_off = BROW_OFF;
    const int bcol_off = BCOL_OFF;
    const int trow = (lane & 7) + ((lane >> 3) & 1) * 8;
    const int tcol = (lane >> 4) * 16;

    float o[2][8][4] = {};
    float lsum[2][2] = {};

    for (int t = 0; t < NT; t++) {
        if (t + 2 < NT) {
            prefetch(t + 2, sb + BUF_BASE + ((t + 2) % NSTAGE) * BUF_SZ);
            CPA_COMMIT;
            CPA_WAIT2;
        } else if (t + 1 < NT) {
            CPA_WAIT1;
        } else {
            CPA_WAIT0;
        }
        __syncthreads();

        const uint32_t bb = sb + BUF_BASE + (t % NSTAGE) * BUF_SZ;

        // ---- S(log2) = Q @ K^T for this warp's kv64; P = ex2(S) ----
        uint32_t ph[2][8][2];
#pragma unroll
        for (int j = 0; j < 4; j++) {
            const int jb = ni * 64 + j * 16;
            float c[2][2][4] = {};
#pragma unroll
            for (int kk = 0; kk < 4; kk++) {
                uint32_t off = swz128((uint32_t)((jb + brow_off) * 128 +
                                                 kk * 32 + bcol_off));
                uint32_t bh[4];
                ldsm_x4(bh, bb + KBH + off);
#pragma unroll
                for (int st = 0; st < 2; st++) {
                    mma16816(c[st][0], aqh[st][kk], bh);
                    mma16816(c[st][1], aqh[st][kk], bh + 2);
                }
            }
#pragma unroll
            for (int st = 0; st < 2; st++)
#pragma unroll
                for (int half = 0; half < 2; half++) {
                    float* cc = c[st][half];
                    uint32_t p01 = ex2_h2(pack_h2(cc[0], cc[1]));
                    uint32_t p23 = ex2_h2(pack_h2(cc[2], cc[3]));
                    float2 f01 = __half22float2(*reinterpret_cast<__half2*>(&p01));
                    float2 f23 = __half22float2(*reinterpret_cast<__half2*>(&p23));
                    lsum[st][0] += f01.x + f01.y;
                    lsum[st][1] += f23.x + f23.y;
                    ph[st][2 * j + half][0] = p01;
                    ph[st][2 * j + half][1] = p23;
                }
        }

        // ---- O += P @ V over this warp's kv64 (V [kv][dh], trans ldsm) ----
#pragma unroll
        for (int kk = 0; kk < 4; kk++) {
            const int vrow = ni * 64 + kk * 16;
#pragma unroll
            for (int n = 0; n < 4; n++) {
                uint32_t off = swz128((uint32_t)((vrow + trow) * 128 +
                                                 n * 32 + tcol));
                uint32_t bh[4];
                ldsm_x4t(bh, bb + VBH + off);
#pragma unroll
                for (int st = 0; st < 2; st++) {
                    uint32_t ah[4] = {ph[st][2 * kk][0], ph[st][2 * kk][1],
                                      ph[st][2 * kk + 1][0], ph[st][2 * kk + 1][1]};
                    mma16816(o[st][2 * n], ah, bh);
                    mma16816(o[st][2 * n + 1], ah, bh + 2);
                }
            }
        }

        __syncthreads();
    }

    // quad-reduce lsum (sum over the 8 kv columns a quad covers per n8 block)
#pragma unroll
    for (int st = 0; st < 2; st++)
#pragma unroll
        for (int e = 0; e < 2; e++) {
            lsum[st][e] += __shfl_xor_sync(0xffffffffu, lsum[st][e], 1);
            lsum[st][e] += __shfl_xor_sync(0xffffffffu, lsum[st][e], 2);
        }

    // ---- cross-ni reduction via smem (KV buffers are free now) ----
    float* ob = (float*)(smem + BUF_BASE);          // [128][64]
    float* ls = (float*)(smem + BUF_BASE + 32768);  // [128]
    const int rl = lane >> 2, cl = (lane & 3) * 2;

    if (ni == 1) {
#pragma unroll
        for (int st = 0; st < 2; st++) {
            int r0 = mrow + st * 16 + rl;
#pragma unroll
            for (int nb = 0; nb < 8; nb++) {
                *(float2*)&ob[r0 * 64 + nb * 8 + cl] =
                    make_float2(o[st][nb][0], o[st][nb][1]);
                *(float2*)&ob[(r0 + 8) * 64 + nb * 8 + cl] =
                    make_float2(o[st][nb][2], o[st][nb][3]);
            }
            if ((lane & 3) == 0) {
                ls[r0] = lsum[st][0];
                ls[r0 + 8] = lsum[st][1];
            }
        }
    }
    __syncthreads();

    if (ni == 0) {
#pragma unroll
        for (int st = 0; st < 2; st++) {
            int r0 = mrow + st * 16 + rl;
            float l0 = lsum[st][0] + ls[r0];
            float l1 = lsum[st][1] + ls[r0 + 8];
            float inv0 = 1.0f / l0;
            float inv1 = 1.0f / l1;
            size_t base0 = ((size_t)(b * S_ + qt * MQ + r0)) * D_ + h * DH_ + cl;
            size_t base1 = base0 + 8 * D_;
#pragma unroll
            for (int nb = 0; nb < 8; nb++) {
                float2 p0 = *(float2*)&ob[r0 * 64 + nb * 8 + cl];
                float2 p1 = *(float2*)&ob[(r0 + 8) * 64 + nb * 8 + cl];
                float v0 = (o[st][nb][0] + p0.x) * inv0;
                float v1 = (o[st][nb][1] + p0.y) * inv0;
                float v2 = (o[st][nb][2] + p1.x) * inv1;
                float v3 = (o[st][nb][3] + p1.y) * inv1;
                float h0 = __half2float(__float2half_rn(v0));
                float h1 = __half2float(__float2half_rn(v1));
                float h2 = __half2float(__float2half_rn(v2));
                float h3 = __half2float(__float2half_rn(v3));
                *(uint32_t*)&g_ctxh[base0 + 8 * nb] = pack_h2(h0, h1);
                *(uint32_t*)&g_ctxl[base0 + 8 * nb] = pack_h2(v0 - h0, v1 - h1);
                *(uint32_t*)&g_ctxh[base1 + 8 * nb] = pack_h2(h2, h3);
                *(uint32_t*)&g_ctxl[base1 + 8 * nb] = pack_h2(v2 - h2, v3 - h3);
            }
        }
    }
}

// ---------------------------------------------------------------------------
extern "C" void kernel_launch(void* const* d_in, const int* in_sizes, int n_in,
                              void* d_out, int out_size)
{
    (void)in_sizes; (void)n_in; (void)out_size;
    const float* x  = (const float*)d_in[0];
    const float* wq = (const float*)d_in[1];
    const float* wk = (const float*)d_in[2];
    const float* wv = (const float*)d_in[3];
    const float* wo = (const float*)d_in[4];
    const float* bo = (const float*)d_in[5];
    float* out = (float*)d_out;

    cudaFuncSetAttribute(attn_kernel,
                         cudaFuncAttributeMaxDynamicSharedMemorySize, ATTN_SMEM);
    cudaFuncSetAttribute(qkv_hmma,
                         cudaFuncAttributeMaxDynamicSharedMemorySize, GEMM_SMEM);
    cudaFuncSetAttribute(out_hmma,
                         cudaFuncAttributeMaxDynamicSharedMemorySize, GEMM_SMEM);

    dim3 gc(256, 4);
    conv_w<<<gc, 256>>>(wq, wk, wv, wo);

    dim3 g1(128, 1, 3);
    qkv_hmma<<<g1, 256, GEMM_SMEM>>>(x);

    dim3 g2(S_ / MQ, H_, B_);
    attn_kernel<<<g2, 256, ATTN_SMEM>>>();

    dim3 g3(128, 4);
    out_hmma<<<g3, 256, GEMM_SMEM>>>(bo, out);
}

// round 10
// speedup vs baseline: 1.0770x; 1.0770x over previous
#include <cuda_runtime.h>
#include <cuda_fp16.h>
#include <cstdint>
#include <math.h>

#define B_ 8
#define S_ 2048
#define D_ 256
#define H_ 4
#define DH_ 64

#define QKV_ELEMS ((size_t)B_ * H_ * S_ * DH_)
#define CTX_ELEMS ((size_t)B_ * S_ * D_)

// Scratch (allocation-free rule: __device__ globals)
__device__ __half g_q16h[QKV_ELEMS];   // [b,h,s,dh], pre-scaled by log2e/8
__device__ __half g_k16h[QKV_ELEMS];   // [b,h,s,dh]
__device__ __half g_v16h[QKV_ELEMS];   // [b,h,s,dh]  (ldsm.trans in attention)
__device__ __half g_ctxh[CTX_ELEMS];   // [b*s, 256]
__device__ __half g_ctxl[CTX_ELEMS];
__device__ __half g_w16h[4 * 256 * 256];  // [mat][n][k] transposed, mats: q,k,v,o
__device__ __half g_w16l[4 * 256 * 256];

// ---------------------------------------------------------------------------
// helpers
// ---------------------------------------------------------------------------
__device__ __forceinline__ uint32_t smem_u32(const void* p) {
    uint32_t a;
    asm("{ .reg .u64 t; cvta.to.shared.u64 t, %1; cvt.u32.u64 %0, t; }"
        : "=r"(a) : "l"(p));
    return a;
}
__device__ __forceinline__ uint32_t swz128(uint32_t x) {
    return x ^ ((x >> 3) & 0x70);
}
__device__ __forceinline__ void ldsm_x4(uint32_t* r, uint32_t addr) {
    asm volatile("ldmatrix.sync.aligned.m8n8.x4.shared.b16 {%0,%1,%2,%3}, [%4];"
                 : "=r"(r[0]), "=r"(r[1]), "=r"(r[2]), "=r"(r[3]) : "r"(addr));
}
__device__ __forceinline__ void ldsm_x4t(uint32_t* r, uint32_t addr) {
    asm volatile("ldmatrix.sync.aligned.m8n8.x4.trans.shared.b16 {%0,%1,%2,%3}, [%4];"
                 : "=r"(r[0]), "=r"(r[1]), "=r"(r[2]), "=r"(r[3]) : "r"(addr));
}
__device__ __forceinline__ void mma16816(float* c, const uint32_t* a, const uint32_t* b) {
    asm volatile("mma.sync.aligned.m16n8k16.row.col.f32.f16.f16.f32 "
                 "{%0,%1,%2,%3}, {%4,%5,%6,%7}, {%8,%9}, {%0,%1,%2,%3};"
                 : "+f"(c[0]), "+f"(c[1]), "+f"(c[2]), "+f"(c[3])
                 : "r"(a[0]), "r"(a[1]), "r"(a[2]), "r"(a[3]),
                   "r"(b[0]), "r"(b[1]));
}
__device__ __forceinline__ uint32_t pack_h2(float lo, float hi) {
    __half2 h = __floats2half2_rn(lo, hi);
    return *reinterpret_cast<uint32_t*>(&h);
}
__device__ __forceinline__ uint32_t ex2_h2(uint32_t a) {
    uint32_t d;
    asm("ex2.approx.f16x2 %0, %1;" : "=r"(d) : "r"(a));
    return d;
}
__device__ __forceinline__ void cpa16(uint32_t dst, const void* src) {
    asm volatile("cp.async.cg.shared.global [%0], [%1], 16;"
                 :: "r"(dst), "l"(src) : "memory");
}
#define CPA_COMMIT asm volatile("cp.async.commit_group;" ::: "memory")
#define CPA_WAIT1 asm volatile("cp.async.wait_group 1;" ::: "memory")
#define CPA_WAIT0 asm volatile("cp.async.wait_group 0;" ::: "memory")

// ---------------------------------------------------------------------------
// One-time weight conversion: fp32 [k][n] -> fp16 hi/lo transposed [n][k]
// ---------------------------------------------------------------------------
__global__ __launch_bounds__(256) void conv_w(
    const float* __restrict__ wq, const float* __restrict__ wk,
    const float* __restrict__ wv, const float* __restrict__ wo)
{
    const int mat = blockIdx.y;
    const float* w = (mat == 0) ? wq : (mat == 1) ? wk : (mat == 2) ? wv : wo;
    int idx = blockIdx.x * 256 + threadIdx.x;
    int n = idx >> 8, k = idx & 255;
    float v = w[k * 256 + n];
    __half hi = __float2half_rn(v);
    g_w16h[mat * 65536 + idx] = hi;
    g_w16l[mat * 65536 + idx] = __float2half_rn(v - __half2float(hi));
}

// ---------------------------------------------------------------------------
// shared GEMM smem layout (192KB)
// ---------------------------------------------------------------------------
#define GX_H 0
#define GX_L 65536
#define GW_H 131072      // qkv: 2 chunk buffers x 32KB; out: hi slab
#define GW_L 163840
#define GEMM_SMEM 196608

#define BROW_OFF ((lane & 7) + ((lane & 16) >> 1))
#define BCOL_OFF ((lane & 8) << 1)

__device__ __forceinline__ void load_w_slab(uint32_t sb, const __half* wh,
                                            const __half* wl, int tid) {
#pragma unroll
    for (int i = tid; i < 2048; i += 256) {
        int r = i >> 5, c = i & 31;
        uint32_t so = (uint32_t)(c >> 3) * 8192 +
                      swz128((uint32_t)(r * 128 + ((c & 7) << 4)));
        cpa16(sb + GW_H + so, wh + r * 256 + c * 8);
        cpa16(sb + GW_L + so, wl + r * 256 + c * 8);
    }
}

// qkv W chunk: 64 n-rows x 128 k (k-half kh), hi+lo -> 32KB chunk buffer
__device__ __forceinline__ void load_w_chunk(uint32_t dst, const __half* wh,
                                             const __half* wl, int kh, int tid) {
#pragma unroll
    for (int i = tid; i < 1024; i += 256) {
        int r = i >> 4, cp = i & 15;
        uint32_t so = (uint32_t)(cp >> 3) * 8192 +
                      swz128((uint32_t)(r * 128 + ((cp & 7) << 4)));
        int gof = r * 256 + (kh * 16 + cp) * 8;
        cpa16(dst + so, wh + gof);
        cpa16(dst + 16384 + so, wl + gof);
    }
}

// ---------------------------------------------------------------------------
// Fused QKV projection (single kernel, all 3 matrices per CTA).
// grid(128). X converted fp32->fp16 hi/lo ONCE, 24 pipelined W chunks
// (z x nb x kh), ILP-reordered inner loop (8 independent MMAs per group).
// ---------------------------------------------------------------------------
__global__ __launch_bounds__(256) void qkv_hmma(const float* __restrict__ x)
{
    extern __shared__ __align__(1024) char smem[];
    const int tid = threadIdx.x;
    const int wid = tid >> 5, lane = tid & 31;
    const int m0 = blockIdx.x * 128;
    const uint32_t sb = smem_u32(smem);

    // start chunk 0 DMA first (z=0, nb=0, kh=0)
    load_w_chunk(sb + GW_H, g_w16h, g_w16l, 0, tid);
    CPA_COMMIT;

    // X tile: fp32 -> fp16 hi/lo panels (once for all 3 matrices)
    for (int i = tid; i < 8192; i += 256) {
        int r = i >> 6;
        int kc = (i & 63) << 2;
        float4 v = *reinterpret_cast<const float4*>(x + (size_t)(m0 + r) * 256 + kc);
        float hx = __half2float(__float2half_rn(v.x));
        float hy = __half2float(__float2half_rn(v.y));
        float hz = __half2float(__float2half_rn(v.z));
        float hw = __half2float(__float2half_rn(v.w));
        uint32_t so = (uint32_t)(kc >> 6) * 16384 +
                      swz128((uint32_t)(r * 128 + (kc & 63) * 2));
        *(uint32_t*)(smem + GX_H + so)     = pack_h2(hx, hy);
        *(uint32_t*)(smem + GX_H + so + 4) = pack_h2(hz, hw);
        *(uint32_t*)(smem + GX_L + so)     = pack_h2(v.x - hx, v.y - hy);
        *(uint32_t*)(smem + GX_L + so + 4) = pack_h2(v.z - hz, v.w - hw);
    }

    const int b = m0 >> 11;
    const int row0 = m0 + wid * 16 + (lane >> 2);
    const int s0 = row0 & 2047;
    const float QSCALE = 0.125f * 1.44269504f;   // 1/sqrt(64) * log2(e)

    float acc[8][4];

    for (int c = 0; c < 24; c++) {
        const int z = c >> 3, nb = (c >> 1) & 3, kh = c & 1;
        if (c + 1 < 24) {
            const int c1 = c + 1;
            const int z1 = c1 >> 3, nb1 = (c1 >> 1) & 3, kh1 = c1 & 1;
            load_w_chunk(sb + GW_H + (c1 & 1) * 32768,
                         g_w16h + z1 * 65536 + nb1 * 64 * 256,
                         g_w16l + z1 * 65536 + nb1 * 64 * 256, kh1, tid);
            CPA_COMMIT;
            CPA_WAIT1;
        } else {
            CPA_WAIT0;
        }
        __syncthreads();

        if (kh == 0) {
#pragma unroll
            for (int j = 0; j < 8; j++)
#pragma unroll
                for (int e = 0; e < 4; e++) acc[j][e] = 0.f;
        }

        const uint32_t wb = sb + GW_H + (c & 1) * 32768;
#pragma unroll
        for (int kk = 0; kk < 8; kk++) {
            const int kk2 = kh * 8 + kk;
            uint32_t aoff = (uint32_t)(kk2 >> 2) * 16384 +
                swz128((uint32_t)((wid * 16 + (lane & 15)) * 128 +
                                  (kk2 & 3) * 32 + (lane >> 4) * 16));
            uint32_t ah[4], al[4];
            ldsm_x4(ah, sb + GX_H + aoff);
            ldsm_x4(al, sb + GX_L + aoff);
            uint32_t bh[4][4], bl[4][4];
#pragma unroll
            for (int j = 0; j < 4; j++) {
                uint32_t boff = (uint32_t)(kk >> 2) * 8192 +
                    swz128((uint32_t)((16 * j + BROW_OFF) * 128 +
                                      (kk & 3) * 32 + BCOL_OFF));
                ldsm_x4(bh[j], wb + boff);
                ldsm_x4(bl[j], wb + 16384 + boff);
            }
#pragma unroll
            for (int j = 0; j < 4; j++) {
                mma16816(acc[2 * j], ah, bh[j]);
                mma16816(acc[2 * j + 1], ah, bh[j] + 2);
            }
#pragma unroll
            for (int j = 0; j < 4; j++) {
                mma16816(acc[2 * j], ah, bl[j]);
                mma16816(acc[2 * j + 1], ah, bl[j] + 2);
            }
#pragma unroll
            for (int j = 0; j < 4; j++) {
                mma16816(acc[2 * j], al, bh[j]);
                mma16816(acc[2 * j + 1], al, bh[j] + 2);
            }
        }

        if (kh == 1) {
            const int h = nb;
            if (z == 0) {
                __half* q = g_q16h + ((size_t)(b * H_ + h) * S_) * DH_;
#pragma unroll
                for (int j = 0; j < 8; j++) {
                    int d = j * 8 + (lane & 3) * 2;
                    *(uint32_t*)&q[(size_t)s0 * DH_ + d] =
                        pack_h2(acc[j][0] * QSCALE, acc[j][1] * QSCALE);
                    *(uint32_t*)&q[(size_t)(s0 + 8) * DH_ + d] =
                        pack_h2(acc[j][2] * QSCALE, acc[j][3] * QSCALE);
                }
            } else {
                __half* dst = ((z == 1) ? g_k16h : g_v16h) +
                              ((size_t)(b * H_ + h) * S_) * DH_;
#pragma unroll
                for (int j = 0; j < 8; j++) {
                    int d = j * 8 + (lane & 3) * 2;
                    *(uint32_t*)&dst[(size_t)s0 * DH_ + d] =
                        pack_h2(acc[j][0], acc[j][1]);
                    *(uint32_t*)&dst[(size_t)(s0 + 8) * DH_ + d] =
                        pack_h2(acc[j][2], acc[j][3]);
                }
            }
        }
        __syncthreads();
    }
}

// ---------------------------------------------------------------------------
// Output projection, fp16 HMMA, 3-term split, ILP-reordered inner loop.
// ---------------------------------------------------------------------------
__global__ __launch_bounds__(256) void out_hmma(
    const float* __restrict__ bo, float* __restrict__ out)
{
    extern __shared__ __align__(1024) char smem[];
    const int tid = threadIdx.x;
    const int wid = tid >> 5, lane = tid & 31;
    const int m0 = blockIdx.x * 128;
    const int n0 = blockIdx.y * 64;
    const uint32_t sb = smem_u32(smem);

    for (int i = tid; i < 4096; i += 256) {
        int r = i >> 5, c = i & 31;
        uint32_t so = (uint32_t)(c >> 3) * 16384 +
                      swz128((uint32_t)(r * 128 + ((c & 7) << 4)));
        cpa16(sb + GX_H + so, g_ctxh + (size_t)(m0 + r) * 256 + c * 8);
        cpa16(sb + GX_L + so, g_ctxl + (size_t)(m0 + r) * 256 + c * 8);
    }
    load_w_slab(sb, g_w16h + 3 * 65536 + n0 * 256,
                    g_w16l + 3 * 65536 + n0 * 256, tid);
    CPA_COMMIT; CPA_WAIT0;
    __syncthreads();

    float acc[8][4] = {};
#pragma unroll
    for (int kk = 0; kk < 16; kk++) {
        uint32_t aoff = (uint32_t)(kk >> 2) * 16384 +
            swz128((uint32_t)((wid * 16 + (lane & 15)) * 128 +
                              (kk & 3) * 32 + (lane >> 4) * 16));
        uint32_t ah[4], al[4];
        ldsm_x4(ah, sb + GX_H + aoff);
        ldsm_x4(al, sb + GX_L + aoff);
        uint32_t bh[4][4], bl[4][4];
#pragma unroll
        for (int j = 0; j < 4; j++) {
            uint32_t boff = (uint32_t)(kk >> 2) * 8192 +
                swz128((uint32_t)((16 * j + BROW_OFF) * 128 +
                                  (kk & 3) * 32 + BCOL_OFF));
            ldsm_x4(bh[j], sb + GW_H + boff);
            ldsm_x4(bl[j], sb + GW_L + boff);
        }
#pragma unroll
        for (int j = 0; j < 4; j++) {
            mma16816(acc[2 * j], ah, bh[j]);
            mma16816(acc[2 * j + 1], ah, bh[j] + 2);
        }
#pragma unroll
        for (int j = 0; j < 4; j++) {
            mma16816(acc[2 * j], ah, bl[j]);
            mma16816(acc[2 * j + 1], ah, bl[j] + 2);
        }
#pragma unroll
        for (int j = 0; j < 4; j++) {
            mma16816(acc[2 * j], al, bh[j]);
            mma16816(acc[2 * j + 1], al, bh[j] + 2);
        }
    }

    const int row0 = m0 + wid * 16 + (lane >> 2);
#pragma unroll
    for (int j = 0; j < 8; j++) {
        int n = n0 + j * 8 + (lane & 3) * 2;
        float2 bias = *reinterpret_cast<const float2*>(bo + n);
        float2 v0 = {acc[j][0] + bias.x, acc[j][1] + bias.y};
        float2 v1 = {acc[j][2] + bias.x, acc[j][3] + bias.y};
        *reinterpret_cast<float2*>(out + (size_t)row0 * 256 + n) = v0;
        *reinterpret_cast<float2*>(out + (size_t)(row0 + 8) * 256 + n) = v1;
    }
}

// ---------------------------------------------------------------------------
// fp16 HMMA flash attention (R8 structure — known good).
// Scores in log2 domain -> softmax via ex2.approx.f16x2.
// V in [s][dh] layout, PV B-fragments via ldmatrix.trans.
// 80KB smem -> 2 CTAs/SM. Fixed softmax max m=0.
// ---------------------------------------------------------------------------
#define MQ 128
#define NKV 128

#define QH_OFF 0            // 128 x 128B  (Q hi, fp16, scaled)
#define BUF_BASE 16384      // 2 buffers x 32KB
#define KBH 0               // K tile 16KB (128 kv x 128B)
#define VBH 16384           // V tile 16KB (128 kv x 128B)
#define BUF_SZ 32768
#define ATTN_SMEM (16384 + 2 * BUF_SZ)

__global__ __launch_bounds__(256, 2) void attn_kernel()
{
    extern __shared__ __align__(1024) char smem[];
    const int tid = threadIdx.x;
    const int wid = tid >> 5, lane = tid & 31;
    const int qt = blockIdx.x, h = blockIdx.y, b = blockIdx.z;
    const uint32_t sb = smem_u32(smem);

    const size_t hb = (size_t)(b * H_ + h);
    const char* qh  = (const char*)(g_q16h + (hb * S_ + (size_t)qt * MQ) * DH_);
    const char* kh0 = (const char*)(g_k16h + hb * S_ * DH_);
    const char* vh0 = (const char*)(g_v16h + hb * S_ * DH_);

    for (int i = tid; i < 1024; i += 256) {
        int r = i >> 3, c = (i & 7) << 4;
        uint32_t so = swz128((uint32_t)(r * 128 + c));
        *(float4*)(smem + QH_OFF + so) = *(const float4*)(qh + r * 128 + c);
    }

    const int kr = tid >> 3, kc = (tid & 7) << 4;

    auto prefetch = [&](int t, uint32_t bb) {
        const char* kh = kh0 + (size_t)t * 128 * 128;
        const char* vh = vh0 + (size_t)t * 128 * 128;
#pragma unroll
        for (int s = 0; s < 4; s++) {
            int r = kr + s * 32;
            uint32_t so = swz128((uint32_t)(r * 128 + kc));
            cpa16(bb + KBH + so, kh + r * 128 + kc);
            cpa16(bb + VBH + so, vh + r * 128 + kc);
        }
    };

    prefetch(0, sb + BUF_BASE);
    CPA_COMMIT;
    __syncthreads();

    const int mrow = wid * 16;
    uint32_t aqh[4][4];
#pragma unroll
    for (int kk = 0; kk < 4; kk++) {
        uint32_t off = swz128((uint32_t)((mrow + (lane & 15)) * 128 +
                                         kk * 32 + (lane >> 4) * 16));
        ldsm_x4(aqh[kk], sb + QH_OFF + off);
    }

    const int brow_off = BROW_OFF;
    const int bcol_off = BCOL_OFF;
    const int trow = (lane & 7) + ((lane >> 3) & 1) * 8;
    const int tcol = (lane >> 4) * 16;

    float o[8][4] = {};
    float lsum0 = 0.0f, lsum1 = 0.0f;
    int buf = 0;

    for (int t = 0; t < S_ / NKV; t++) {
        if (t + 1 < S_ / NKV) {
            prefetch(t + 1, sb + BUF_BASE + (buf ^ 1) * BUF_SZ);
            CPA_COMMIT;
            CPA_WAIT1;
        } else {
            CPA_WAIT0;
        }
        __syncthreads();

        const uint32_t bb = sb + BUF_BASE + buf * BUF_SZ;

        // ---- S(log2) = Q @ K^T; P = ex2(S) packed fp16 ----
        uint32_t ph[16][2];
#pragma unroll
        for (int j = 0; j < 8; j++) {
            float c0[4] = {0.f, 0.f, 0.f, 0.f};
            float c1[4] = {0.f, 0.f, 0.f, 0.f};
#pragma unroll
            for (int kk = 0; kk < 4; kk++) {
                uint32_t off = swz128((uint32_t)((16 * j + brow_off) * 128 +
                                                 kk * 32 + bcol_off));
                uint32_t bh[4];
                ldsm_x4(bh, bb + KBH + off);
                mma16816(c0, aqh[kk], bh);
                mma16816(c1, aqh[kk], bh + 2);
            }
#pragma unroll
            for (int half = 0; half < 2; half++) {
                float* c = half ? c1 : c0;
                uint32_t p01 = ex2_h2(pack_h2(c[0], c[1]));
                uint32_t p23 = ex2_h2(pack_h2(c[2], c[3]));
                float2 f01 = __half22float2(*reinterpret_cast<__half2*>(&p01));
                float2 f23 = __half22float2(*reinterpret_cast<__half2*>(&p23));
                lsum0 += f01.x + f01.y;
                lsum1 += f23.x + f23.y;
                ph[2 * j + half][0] = p01;
                ph[2 * j + half][1] = p23;
            }
        }

        // ---- O += P @ V (V row-major [kv][dh], trans ldsm) ----
#pragma unroll
        for (int kk = 0; kk < 8; kk++) {
            uint32_t ah[4] = {ph[2 * kk][0], ph[2 * kk][1],
                              ph[2 * kk + 1][0], ph[2 * kk + 1][1]};
#pragma unroll
            for (int n = 0; n < 4; n++) {
                uint32_t off = swz128((uint32_t)((16 * kk + trow) * 128 +
                                                 n * 32 + tcol));
                uint32_t bh[4];
                ldsm_x4t(bh, bb + VBH + off);
                mma16816(o[2 * n], ah, bh);
                mma16816(o[2 * n + 1], ah, bh + 2);
            }
        }

        __syncthreads();
        buf ^= 1;
    }

    lsum0 += __shfl_xor_sync(0xffffffffu, lsum0, 1);
    lsum0 += __shfl_xor_sync(0xffffffffu, lsum0, 2);
    lsum1 += __shfl_xor_sync(0xffffffffu, lsum1, 1);
    lsum1 += __shfl_xor_sync(0xffffffffu, lsum1, 2);
    const float inv0 = 1.0f / lsum0;
    const float inv1 = 1.0f / lsum1;

    const int r0 = qt * MQ + mrow + (lane >> 2);
    size_t base0 = ((size_t)(b * S_ + r0)) * D_ + h * DH_ + (lane & 3) * 2;
    size_t base1 = base0 + 8 * D_;
#pragma unroll
    for (int n = 0; n < 8; n++) {
        float v0 = o[n][0] * inv0, v1 = o[n][1] * inv0;
        float v2 = o[n][2] * inv1, v3 = o[n][3] * inv1;
        float h0 = __half2float(__float2half_rn(v0));
        float h1 = __half2float(__float2half_rn(v1));
        float h2 = __half2float(__float2half_rn(v2));
        float h3 = __half2float(__float2half_rn(v3));
        *(uint32_t*)&g_ctxh[base0 + 8 * n] = pack_h2(h0, h1);
        *(uint32_t*)&g_ctxl[base0 + 8 * n] = pack_h2(v0 - h0, v1 - h1);
        *(uint32_t*)&g_ctxh[base1 + 8 * n] = pack_h2(h2, h3);
        *(uint32_t*)&g_ctxl[base1 + 8 * n] = pack_h2(v2 - h2, v3 - h3);
    }
}

// ---------------------------------------------------------------------------
extern "C" void kernel_launch(void* const* d_in, const int* in_sizes, int n_in,
                              void* d_out, int out_size)
{
    (void)in_sizes; (void)n_in; (void)out_size;
    const float* x  = (const float*)d_in[0];
    const float* wq = (const float*)d_in[1];
    const float* wk = (const float*)d_in[2];
    const float* wv = (const float*)d_in[3];
    const float* wo = (const float*)d_in[4];
    const float* bo = (const float*)d_in[5];
    float* out = (float*)d_out;

    cudaFuncSetAttribute(attn_kernel,
                         cudaFuncAttributeMaxDynamicSharedMemorySize, ATTN_SMEM);
    cudaFuncSetAttribute(qkv_hmma,
                         cudaFuncAttributeMaxDynamicSharedMemorySize, GEMM_SMEM);
    cudaFuncSetAttribute(out_hmma,
                         cudaFuncAttributeMaxDynamicSharedMemorySize, GEMM_SMEM);

    dim3 gc(256, 4);
    conv_w<<<gc, 256>>>(wq, wk, wv, wo);

    qkv_hmma<<<128, 256, GEMM_SMEM>>>(x);

    dim3 g2(S_ / MQ, H_, B_);
    attn_kernel<<<g2, 256, ATTN_SMEM>>>();

    dim3 g3(128, 4);
    out_hmma<<<g3, 256, GEMM_SMEM>>>(bo, out);
}

// round 11
// speedup vs baseline: 1.2350x; 1.1467x over previous
#include <cuda_runtime.h>
#include <cuda_fp16.h>
#include <cstdint>
#include <math.h>

#define B_ 8
#define S_ 2048
#define D_ 256
#define H_ 4
#define DH_ 64

#define QKV_ELEMS ((size_t)B_ * H_ * S_ * DH_)
#define CTX_ELEMS ((size_t)B_ * S_ * D_)

// Scratch (allocation-free rule: __device__ globals)
__device__ __half g_q16h[QKV_ELEMS];   // [b,h,s,dh], pre-scaled by log2e/8
__device__ __half g_k16h[QKV_ELEMS];   // [b,h,s,dh]
__device__ __half g_v16h[QKV_ELEMS];   // [b,h,s,dh]  (ldsm.trans in attention)
__device__ __half g_ctxh[CTX_ELEMS];   // [b*s, 256]  (single fp16)
__device__ __half g_w16h[4 * 256 * 256];  // [mat][n][k] transposed, mats: q,k,v,o
__device__ __half g_w16l[4 * 256 * 256];

// ---------------------------------------------------------------------------
// helpers
// ---------------------------------------------------------------------------
__device__ __forceinline__ uint32_t smem_u32(const void* p) {
    uint32_t a;
    asm("{ .reg .u64 t; cvta.to.shared.u64 t, %1; cvt.u32.u64 %0, t; }"
        : "=r"(a) : "l"(p));
    return a;
}
__device__ __forceinline__ uint32_t swz128(uint32_t x) {
    return x ^ ((x >> 3) & 0x70);
}
__device__ __forceinline__ void ldsm_x4(uint32_t* r, uint32_t addr) {
    asm volatile("ldmatrix.sync.aligned.m8n8.x4.shared.b16 {%0,%1,%2,%3}, [%4];"
                 : "=r"(r[0]), "=r"(r[1]), "=r"(r[2]), "=r"(r[3]) : "r"(addr));
}
__device__ __forceinline__ void ldsm_x4t(uint32_t* r, uint32_t addr) {
    asm volatile("ldmatrix.sync.aligned.m8n8.x4.trans.shared.b16 {%0,%1,%2,%3}, [%4];"
                 : "=r"(r[0]), "=r"(r[1]), "=r"(r[2]), "=r"(r[3]) : "r"(addr));
}
__device__ __forceinline__ void mma16816(float* c, const uint32_t* a, const uint32_t* b) {
    asm volatile("mma.sync.aligned.m16n8k16.row.col.f32.f16.f16.f32 "
                 "{%0,%1,%2,%3}, {%4,%5,%6,%7}, {%8,%9}, {%0,%1,%2,%3};"
                 : "+f"(c[0]), "+f"(c[1]), "+f"(c[2]), "+f"(c[3])
                 : "r"(a[0]), "r"(a[1]), "r"(a[2]), "r"(a[3]),
                   "r"(b[0]), "r"(b[1]));
}
__device__ __forceinline__ uint32_t pack_h2(float lo, float hi) {
    __half2 h = __floats2half2_rn(lo, hi);
    return *reinterpret_cast<uint32_t*>(&h);
}
__device__ __forceinline__ uint32_t ex2_h2(uint32_t a) {
    uint32_t d;
    asm("ex2.approx.f16x2 %0, %1;" : "=r"(d) : "r"(a));
    return d;
}
__device__ __forceinline__ void cpa16(uint32_t dst, const void* src) {
    asm volatile("cp.async.cg.shared.global [%0], [%1], 16;"
                 :: "r"(dst), "l"(src) : "memory");
}
#define CPA_COMMIT asm volatile("cp.async.commit_group;" ::: "memory")
#define CPA_WAIT1 asm volatile("cp.async.wait_group 1;" ::: "memory")
#define CPA_WAIT0 asm volatile("cp.async.wait_group 0;" ::: "memory")

// ---------------------------------------------------------------------------
// One-time weight conversion: fp32 [k][n] -> fp16 hi/lo transposed [n][k]
// ---------------------------------------------------------------------------
__global__ __launch_bounds__(256) void conv_w(
    const float* __restrict__ wq, const float* __restrict__ wk,
    const float* __restrict__ wv, const float* __restrict__ wo)
{
    const int mat = blockIdx.y;
    const float* w = (mat == 0) ? wq : (mat == 1) ? wk : (mat == 2) ? wv : wo;
    int idx = blockIdx.x * 256 + threadIdx.x;
    int n = idx >> 8, k = idx & 255;
    float v = w[k * 256 + n];
    __half hi = __float2half_rn(v);
    g_w16h[mat * 65536 + idx] = hi;
    g_w16l[mat * 65536 + idx] = __float2half_rn(v - __half2float(hi));
}

// ---------------------------------------------------------------------------
// shared GEMM smem layout (128KB): X hi 64KB + 2 W chunk buffers x 32KB
// ---------------------------------------------------------------------------
#define GX_H 0
#define GW_B 65536
#define GEMM_SMEM 131072

#define BROW_OFF ((lane & 7) + ((lane & 16) >> 1))
#define BCOL_OFF ((lane & 8) << 1)

// W chunk: 64 n-rows x 128 k (k-half kh), hi+lo -> 32KB chunk buffer
__device__ __forceinline__ void load_w_chunk(uint32_t dst, const __half* wh,
                                             const __half* wl, int kh, int tid) {
#pragma unroll
    for (int i = tid; i < 1024; i += 256) {
        int r = i >> 4, cp = i & 15;
        uint32_t so = (uint32_t)(cp >> 3) * 8192 +
                      swz128((uint32_t)(r * 128 + ((cp & 7) << 4)));
        int gof = r * 256 + (kh * 16 + cp) * 8;
        cpa16(dst + so, wh + gof);
        cpa16(dst + 16384 + so, wl + gof);
    }
}

// ---------------------------------------------------------------------------
// Fused QKV projection. 2-term split: x_hi x (W_hi + W_lo).
// grid(128). X converted fp32->fp16 ONCE; 24 pipelined W chunks (z,nb,kh).
// ---------------------------------------------------------------------------
__global__ __launch_bounds__(256) void qkv_hmma(const float* __restrict__ x)
{
    extern __shared__ __align__(1024) char smem[];
    const int tid = threadIdx.x;
    const int wid = tid >> 5, lane = tid & 31;
    const int m0 = blockIdx.x * 128;
    const uint32_t sb = smem_u32(smem);

    // start chunk 0 DMA first (z=0, nb=0, kh=0)
    load_w_chunk(sb + GW_B, g_w16h, g_w16l, 0, tid);
    CPA_COMMIT;

    // X tile: fp32 -> fp16 hi panels (once for all 3 matrices)
    for (int i = tid; i < 8192; i += 256) {
        int r = i >> 6;
        int kc = (i & 63) << 2;
        float4 v = *reinterpret_cast<const float4*>(x + (size_t)(m0 + r) * 256 + kc);
        uint32_t so = (uint32_t)(kc >> 6) * 16384 +
                      swz128((uint32_t)(r * 128 + (kc & 63) * 2));
        *(uint32_t*)(smem + GX_H + so)     = pack_h2(v.x, v.y);
        *(uint32_t*)(smem + GX_H + so + 4) = pack_h2(v.z, v.w);
    }

    const int b = m0 >> 11;
    const int row0 = m0 + wid * 16 + (lane >> 2);
    const int s0 = row0 & 2047;
    const float QSCALE = 0.125f * 1.44269504f;   // 1/sqrt(64) * log2(e)

    float acc[8][4];

    for (int c = 0; c < 24; c++) {
        const int z = c >> 3, nb = (c >> 1) & 3, kh = c & 1;
        if (c + 1 < 24) {
            const int c1 = c + 1;
            const int z1 = c1 >> 3, nb1 = (c1 >> 1) & 3, kh1 = c1 & 1;
            load_w_chunk(sb + GW_B + (c1 & 1) * 32768,
                         g_w16h + z1 * 65536 + nb1 * 64 * 256,
                         g_w16l + z1 * 65536 + nb1 * 64 * 256, kh1, tid);
            CPA_COMMIT;
            CPA_WAIT1;
        } else {
            CPA_WAIT0;
        }
        __syncthreads();

        if (kh == 0) {
#pragma unroll
            for (int j = 0; j < 8; j++)
#pragma unroll
                for (int e = 0; e < 4; e++) acc[j][e] = 0.f;
        }

        const uint32_t wb = sb + GW_B + (c & 1) * 32768;
#pragma unroll
        for (int kk = 0; kk < 8; kk++) {
            const int kk2 = kh * 8 + kk;
            uint32_t aoff = (uint32_t)(kk2 >> 2) * 16384 +
                swz128((uint32_t)((wid * 16 + (lane & 15)) * 128 +
                                  (kk2 & 3) * 32 + (lane >> 4) * 16));
            uint32_t ah[4];
            ldsm_x4(ah, sb + GX_H + aoff);
            uint32_t bh[4][4], bl[4][4];
#pragma unroll
            for (int j = 0; j < 4; j++) {
                uint32_t boff = (uint32_t)(kk >> 2) * 8192 +
                    swz128((uint32_t)((16 * j + BROW_OFF) * 128 +
                                      (kk & 3) * 32 + BCOL_OFF));
                ldsm_x4(bh[j], wb + boff);
                ldsm_x4(bl[j], wb + 16384 + boff);
            }
#pragma unroll
            for (int j = 0; j < 4; j++) {
                mma16816(acc[2 * j], ah, bh[j]);
                mma16816(acc[2 * j + 1], ah, bh[j] + 2);
            }
#pragma unroll
            for (int j = 0; j < 4; j++) {
                mma16816(acc[2 * j], ah, bl[j]);
                mma16816(acc[2 * j + 1], ah, bl[j] + 2);
            }
        }

        if (kh == 1) {
            const int h = nb;
            if (z == 0) {
                __half* q = g_q16h + ((size_t)(b * H_ + h) * S_) * DH_;
#pragma unroll
                for (int j = 0; j < 8; j++) {
                    int d = j * 8 + (lane & 3) * 2;
                    *(uint32_t*)&q[(size_t)s0 * DH_ + d] =
                        pack_h2(acc[j][0] * QSCALE, acc[j][1] * QSCALE);
                    *(uint32_t*)&q[(size_t)(s0 + 8) * DH_ + d] =
                        pack_h2(acc[j][2] * QSCALE, acc[j][3] * QSCALE);
                }
            } else {
                __half* dst = ((z == 1) ? g_k16h : g_v16h) +
                              ((size_t)(b * H_ + h) * S_) * DH_;
#pragma unroll
                for (int j = 0; j < 8; j++) {
                    int d = j * 8 + (lane & 3) * 2;
                    *(uint32_t*)&dst[(size_t)s0 * DH_ + d] =
                        pack_h2(acc[j][0], acc[j][1]);
                    *(uint32_t*)&dst[(size_t)(s0 + 8) * DH_ + d] =
                        pack_h2(acc[j][2], acc[j][3]);
                }
            }
        }
        __syncthreads();
    }
}

// ---------------------------------------------------------------------------
// Output projection. 2-term split: ctx_hi x (Wo_hi + Wo_lo).
// grid(128). ctx tile resident (64KB cp.async); 8 pipelined W chunks.
// ---------------------------------------------------------------------------
__global__ __launch_bounds__(256) void out_hmma(
    const float* __restrict__ bo, float* __restrict__ out)
{
    extern __shared__ __align__(1024) char smem[];
    const int tid = threadIdx.x;
    const int wid = tid >> 5, lane = tid & 31;
    const int m0 = blockIdx.x * 128;
    const uint32_t sb = smem_u32(smem);

    const __half* wbh = g_w16h + 3 * 65536;
    const __half* wbl = g_w16l + 3 * 65536;

    // chunk 0 DMA first
    load_w_chunk(sb + GW_B, wbh, wbl, 0, tid);
    CPA_COMMIT;

    // ctx tile (fp16, 64KB) via cp.async
    for (int i = tid; i < 4096; i += 256) {
        int r = i >> 5, c = i & 31;
        uint32_t so = (uint32_t)(c >> 3) * 16384 +
                      swz128((uint32_t)(r * 128 + ((c & 7) << 4)));
        cpa16(sb + GX_H + so, g_ctxh + (size_t)(m0 + r) * 256 + c * 8);
    }
    CPA_COMMIT;

    const int row0 = m0 + wid * 16 + (lane >> 2);
    float acc[8][4];

    for (int c = 0; c < 8; c++) {
        const int nb = c >> 1, kh = c & 1;
        if (c + 1 < 8) {
            const int c1 = c + 1;
            load_w_chunk(sb + GW_B + (c1 & 1) * 32768,
                         wbh + ((c1 >> 1) & 3) * 64 * 256,
                         wbl + ((c1 >> 1) & 3) * 64 * 256, c1 & 1, tid);
            CPA_COMMIT;
            CPA_WAIT1;
        } else {
            CPA_WAIT0;
        }
        __syncthreads();

        if (kh == 0) {
#pragma unroll
            for (int j = 0; j < 8; j++)
#pragma unroll
                for (int e = 0; e < 4; e++) acc[j][e] = 0.f;
        }

        const uint32_t wb = sb + GW_B + (c & 1) * 32768;
#pragma unroll
        for (int kk = 0; kk < 8; kk++) {
            const int kk2 = kh * 8 + kk;
            uint32_t aoff = (uint32_t)(kk2 >> 2) * 16384 +
                swz128((uint32_t)((wid * 16 + (lane & 15)) * 128 +
                                  (kk2 & 3) * 32 + (lane >> 4) * 16));
            uint32_t ah[4];
            ldsm_x4(ah, sb + GX_H + aoff);
            uint32_t bh[4][4], bl[4][4];
#pragma unroll
            for (int j = 0; j < 4; j++) {
                uint32_t boff = (uint32_t)(kk >> 2) * 8192 +
                    swz128((uint32_t)((16 * j + BROW_OFF) * 128 +
                                      (kk & 3) * 32 + BCOL_OFF));
                ldsm_x4(bh[j], wb + boff);
                ldsm_x4(bl[j], wb + 16384 + boff);
            }
#pragma unroll
            for (int j = 0; j < 4; j++) {
                mma16816(acc[2 * j], ah, bh[j]);
                mma16816(acc[2 * j + 1], ah, bh[j] + 2);
            }
#pragma unroll
            for (int j = 0; j < 4; j++) {
                mma16816(acc[2 * j], ah, bl[j]);
                mma16816(acc[2 * j + 1], ah, bl[j] + 2);
            }
        }

        if (kh == 1) {
#pragma unroll
            for (int j = 0; j < 8; j++) {
                int n = nb * 64 + j * 8 + (lane & 3) * 2;
                float2 bias = *reinterpret_cast<const float2*>(bo + n);
                float2 v0 = {acc[j][0] + bias.x, acc[j][1] + bias.y};
                float2 v1 = {acc[j][2] + bias.x, acc[j][3] + bias.y};
                *reinterpret_cast<float2*>(out + (size_t)row0 * 256 + n) = v0;
                *reinterpret_cast<float2*>(out + (size_t)(row0 + 8) * 256 + n) = v1;
            }
        }
        __syncthreads();
    }
}

// ---------------------------------------------------------------------------
// fp16 HMMA flash attention (R8 structure — known good).
// Scores in log2 domain -> softmax via ex2.approx.f16x2.
// V in [s][dh] layout, PV B-fragments via ldmatrix.trans.
// 80KB smem -> 2 CTAs/SM. Fixed softmax max m=0. ctx written single fp16.
// ---------------------------------------------------------------------------
#define MQ 128
#define NKV 128

#define QH_OFF 0            // 128 x 128B  (Q hi, fp16, scaled)
#define BUF_BASE 16384      // 2 buffers x 32KB
#define KBH 0               // K tile 16KB (128 kv x 128B)
#define VBH 16384           // V tile 16KB (128 kv x 128B)
#define BUF_SZ 32768
#define ATTN_SMEM (16384 + 2 * BUF_SZ)

__global__ __launch_bounds__(256, 2) void attn_kernel()
{
    extern __shared__ __align__(1024) char smem[];
    const int tid = threadIdx.x;
    const int wid = tid >> 5, lane = tid & 31;
    const int qt = blockIdx.x, h = blockIdx.y, b = blockIdx.z;
    const uint32_t sb = smem_u32(smem);

    const size_t hb = (size_t)(b * H_ + h);
    const char* qh  = (const char*)(g_q16h + (hb * S_ + (size_t)qt * MQ) * DH_);
    const char* kh0 = (const char*)(g_k16h + hb * S_ * DH_);
    const char* vh0 = (const char*)(g_v16h + hb * S_ * DH_);

    for (int i = tid; i < 1024; i += 256) {
        int r = i >> 3, c = (i & 7) << 4;
        uint32_t so = swz128((uint32_t)(r * 128 + c));
        *(float4*)(smem + QH_OFF + so) = *(const float4*)(qh + r * 128 + c);
    }

    const int kr = tid >> 3, kc = (tid & 7) << 4;

    auto prefetch = [&](int t, uint32_t bb) {
        const char* kh = kh0 + (size_t)t * 128 * 128;
        const char* vh = vh0 + (size_t)t * 128 * 128;
#pragma unroll
        for (int s = 0; s < 4; s++) {
            int r = kr + s * 32;
            uint32_t so = swz128((uint32_t)(r * 128 + kc));
            cpa16(bb + KBH + so, kh + r * 128 + kc);
            cpa16(bb + VBH + so, vh + r * 128 + kc);
        }
    };

    prefetch(0, sb + BUF_BASE);
    CPA_COMMIT;
    __syncthreads();

    const int mrow = wid * 16;
    uint32_t aqh[4][4];
#pragma unroll
    for (int kk = 0; kk < 4; kk++) {
        uint32_t off = swz128((uint32_t)((mrow + (lane & 15)) * 128 +
                                         kk * 32 + (lane >> 4) * 16));
        ldsm_x4(aqh[kk], sb + QH_OFF + off);
    }

    const int brow_off = BROW_OFF;
    const int bcol_off = BCOL_OFF;
    const int trow = (lane & 7) + ((lane >> 3) & 1) * 8;
    const int tcol = (lane >> 4) * 16;

    float o[8][4] = {};
    float lsum0 = 0.0f, lsum1 = 0.0f;
    int buf = 0;

    for (int t = 0; t < S_ / NKV; t++) {
        if (t + 1 < S_ / NKV) {
            prefetch(t + 1, sb + BUF_BASE + (buf ^ 1) * BUF_SZ);
            CPA_COMMIT;
            CPA_WAIT1;
        } else {
            CPA_WAIT0;
        }
        __syncthreads();

        const uint32_t bb = sb + BUF_BASE + buf * BUF_SZ;

        // ---- S(log2) = Q @ K^T; P = ex2(S) packed fp16 ----
        uint32_t ph[16][2];
#pragma unroll
        for (int j = 0; j < 8; j++) {
            float c0[4] = {0.f, 0.f, 0.f, 0.f};
            float c1[4] = {0.f, 0.f, 0.f, 0.f};
#pragma unroll
            for (int kk = 0; kk < 4; kk++) {
                uint32_t off = swz128((uint32_t)((16 * j + brow_off) * 128 +
                                                 kk * 32 + bcol_off));
                uint32_t bh[4];
                ldsm_x4(bh, bb + KBH + off);
                mma16816(c0, aqh[kk], bh);
                mma16816(c1, aqh[kk], bh + 2);
            }
#pragma unroll
            for (int half = 0; half < 2; half++) {
                float* c = half ? c1 : c0;
                uint32_t p01 = ex2_h2(pack_h2(c[0], c[1]));
                uint32_t p23 = ex2_h2(pack_h2(c[2], c[3]));
                float2 f01 = __half22float2(*reinterpret_cast<__half2*>(&p01));
                float2 f23 = __half22float2(*reinterpret_cast<__half2*>(&p23));
                lsum0 += f01.x + f01.y;
                lsum1 += f23.x + f23.y;
                ph[2 * j + half][0] = p01;
                ph[2 * j + half][1] = p23;
            }
        }

        // ---- O += P @ V (V row-major [kv][dh], trans ldsm) ----
#pragma unroll
        for (int kk = 0; kk < 8; kk++) {
            uint32_t ah[4] = {ph[2 * kk][0], ph[2 * kk][1],
                              ph[2 * kk + 1][0], ph[2 * kk + 1][1]};
#pragma unroll
            for (int n = 0; n < 4; n++) {
                uint32_t off = swz128((uint32_t)((16 * kk + trow) * 128 +
                                                 n * 32 + tcol));
                uint32_t bh[4];
                ldsm_x4t(bh, bb + VBH + off);
                mma16816(o[2 * n], ah, bh);
                mma16816(o[2 * n + 1], ah, bh + 2);
            }
        }

        __syncthreads();
        buf ^= 1;
    }

    lsum0 += __shfl_xor_sync(0xffffffffu, lsum0, 1);
    lsum0 += __shfl_xor_sync(0xffffffffu, lsum0, 2);
    lsum1 += __shfl_xor_sync(0xffffffffu, lsum1, 1);
    lsum1 += __shfl_xor_sync(0xffffffffu, lsum1, 2);
    const float inv0 = 1.0f / lsum0;
    const float inv1 = 1.0f / lsum1;

    const int r0 = qt * MQ + mrow + (lane >> 2);
    size_t base0 = ((size_t)(b * S_ + r0)) * D_ + h * DH_ + (lane & 3) * 2;
    size_t base1 = base0 + 8 * D_;
#pragma unroll
    for (int n = 0; n < 8; n++) {
        *(uint32_t*)&g_ctxh[base0 + 8 * n] =
            pack_h2(o[n][0] * inv0, o[n][1] * inv0);
        *(uint32_t*)&g_ctxh[base1 + 8 * n] =
            pack_h2(o[n][2] * inv1, o[n][3] * inv1);
    }
}

// ---------------------------------------------------------------------------
extern "C" void kernel_launch(void* const* d_in, const int* in_sizes, int n_in,
                              void* d_out, int out_size)
{
    (void)in_sizes; (void)n_in; (void)out_size;
    const float* x  = (const float*)d_in[0];
    const float* wq = (const float*)d_in[1];
    const float* wk = (const float*)d_in[2];
    const float* wv = (const float*)d_in[3];
    const float* wo = (const float*)d_in[4];
    const float* bo = (const float*)d_in[5];
    float* out = (float*)d_out;

    cudaFuncSetAttribute(attn_kernel,
                         cudaFuncAttributeMaxDynamicSharedMemorySize, ATTN_SMEM);
    cudaFuncSetAttribute(qkv_hmma,
                         cudaFuncAttributeMaxDynamicSharedMemorySize, GEMM_SMEM);
    cudaFuncSetAttribute(out_hmma,
                         cudaFuncAttributeMaxDynamicSharedMemorySize, GEMM_SMEM);

    dim3 gc(256, 4);
    conv_w<<<gc, 256>>>(wq, wk, wv, wo);

    qkv_hmma<<<128, 256, GEMM_SMEM>>>(x);

    dim3 g2(S_ / MQ, H_, B_);
    attn_kernel<<<g2, 256, ATTN_SMEM>>>();

    out_hmma<<<128, 256, GEMM_SMEM>>>(bo, out);
}